// round 7
// baseline (speedup 1.0000x reference)
#include <cuda_runtime.h>
#include <math.h>

#define B    64
#define T    4096
#define DIM  256
#define NLOC 32
#define KS   31
#define PAD  15
#define TPW  32             // rows per warp
#define WPB  8              // warps per block
#define TPB  (TPW * WPB)    // 256 t per block
#define NCH  (T / TPB)      // 16 chunks per batch -> 1024 blocks

// -------- scratch (static device globals; no allocation allowed) ----------
__device__ float g_u[B * DIM];            // W^T q per batch
__device__ float g_g[B * KS];             // collapsed conv kernel per batch
__device__ float g_cb[B];                 // collapsed conv bias per batch
__device__ float g_energ[B * T];          // raw energies
__device__ float g_pm[B * NCH];           // per-block running max
__device__ float g_ps[B * NCH];           // per-block exp-sum
__device__ float g_pctx[B * NCH * DIM];   // per-block unnormalized context
__device__ int   g_done[B];               // arrival counter per batch

// ---------------------------------------------------------------------------
// Kernel A: prep, parallelized. grid = (B, 9).
//   chunk c in [0,8): u[b, c*32 .. c*32+32) = W^T q slice
//   chunk 8:          v = L^T q ; g = conv_w^T v ; cb = conv_b . v ; reset ctr
// ---------------------------------------------------------------------------
__global__ void __launch_bounds__(256)
prep_kernel(const float* __restrict__ q,
            const float* __restrict__ Ww,
            const float* __restrict__ Lw,
            const float* __restrict__ convw,
            const float* __restrict__ convb) {
    __shared__ float sq[DIM];
    __shared__ float part[8][32];
    __shared__ float sv[NLOC];

    const int b   = blockIdx.x;
    const int c   = blockIdx.y;
    const int tid = threadIdx.x;
    const int ln  = tid & 31;
    const int eg  = tid >> 5;

    sq[tid] = q[b * DIM + tid];
    __syncthreads();

    if (c < 8) {
        const float* wp = Ww + (size_t)(eg * 32) * DIM + c * 32 + ln;
        float acc = 0.f;
#pragma unroll
        for (int e = 0; e < 32; e++)
            acc = fmaf(wp[(size_t)e * DIM], sq[eg * 32 + e], acc);
        part[eg][ln] = acc;
        __syncthreads();
        if (tid < 32) {
            float u = part[0][tid];
#pragma unroll
            for (int j = 1; j < 8; j++) u += part[j][tid];
            g_u[b * DIM + c * 32 + tid] = u;
        }
    } else {
        if (tid == 32) g_done[b] = 0;        // reset tail counter (replay-safe)
        const float* lp = Lw + (size_t)(eg * 32) * NLOC + ln;
        float acc = 0.f;
#pragma unroll
        for (int e = 0; e < 32; e++)
            acc = fmaf(lp[(size_t)e * NLOC], sq[eg * 32 + e], acc);
        part[eg][ln] = acc;
        __syncthreads();
        if (tid < 32) {
            float v = part[0][tid];
#pragma unroll
            for (int j = 1; j < 8; j++) v += part[j][tid];
            sv[tid] = v;
        }
        __syncthreads();
        if (tid < KS) {
            float gg = 0.f;
#pragma unroll
            for (int cc = 0; cc < NLOC; cc++)
                gg = fmaf(convw[cc * KS + tid], sv[cc], gg);
            g_g[b * KS + tid] = gg;
        }
        if (tid == 0) {
            float cb = 0.f;
#pragma unroll
            for (int cc = 0; cc < NLOC; cc++) cb = fmaf(convb[cc], sv[cc], cb);
            g_cb[b] = cb;
        }
    }
}

// ---------------------------------------------------------------------------
// Kernel B: HBM-bound pass + fused per-batch finish tail.
// PDL: phase 1 (mask smem fill, first enc prefetches) runs before
// cudaGridDependencySynchronize(); prep outputs read only after it.
// Last block of each batch (atomic counter) performs combine + context +
// attn epilogue for the batch.
// ---------------------------------------------------------------------------
__global__ void __launch_bounds__(256, 4)
energy_ctx_kernel(const float* __restrict__ enc,
                  const float* __restrict__ mask,
                  float* __restrict__ out) {
    __shared__ float smask[TPB + 2 * PAD];
    __shared__ float red_m[WPB], red_s[WPB];
    __shared__ __align__(16) float red_ctx[WPB][DIM];
    __shared__ int is_last;

    const int b   = blockIdx.x;
    const int ch  = blockIdx.y;
    const int tid = threadIdx.x;
    const int w   = tid >> 5;
    const int l   = tid & 31;
    const int t0  = ch * TPB;

    // ---- phase 1: independent of prep outputs ----
    for (int j = tid; j < TPB + 2 * PAD; j += 256) {
        int gt = t0 - PAD + j;
        smask[j] = (gt >= 0 && gt < T) ? mask[b * T + gt] : 0.f;
    }

    const int tw0 = t0 + w * TPW;
    const float* base = enc + ((size_t)tw0 * B + b) * DIM + l * 8;
    const size_t stride = (size_t)B * DIM;

    float4 pf0[2], pf1[2];
    pf0[0] = *(const float4*)(base);
    pf1[0] = *(const float4*)(base + 4);
    pf0[1] = *(const float4*)(base + stride);
    pf1[1] = *(const float4*)(base + stride + 4);

    // ---- wait for prep (PDL) ----
    cudaGridDependencySynchronize();

    const float4 uA = *(const float4*)(g_u + b * DIM + l * 8);
    const float4 uB = *(const float4*)(g_u + b * DIM + l * 8 + 4);
    const float  gl = (l < KS) ? g_g[b * KS + l] : 0.f;
    const float  cb = g_cb[b];
    __syncthreads();   // smask ready

    float m = -INFINITY, s = 0.f;
    float cx[8] = {0.f, 0.f, 0.f, 0.f, 0.f, 0.f, 0.f, 0.f};

#pragma unroll 4
    for (int i = 0; i < TPW; i++) {
        const int slot = i & 1;
        const float4 a0 = pf0[slot], a1 = pf1[slot];
        if (i + 2 < TPW) {
            const float* np = base + (size_t)(i + 2) * stride;
            pf0[slot] = *(const float4*)np;
            pf1[slot] = *(const float4*)(np + 4);
        }
        const float msk = (l < KS) ? smask[w * TPW + i + l] : 0.f;

        float p;
        p = a0.x * uA.x;
        p = fmaf(a0.y, uA.y, p);
        p = fmaf(a0.z, uA.z, p);
        p = fmaf(a0.w, uA.w, p);
        p = fmaf(a1.x, uB.x, p);
        p = fmaf(a1.y, uB.y, p);
        p = fmaf(a1.z, uB.z, p);
        p = fmaf(a1.w, uB.w, p);
        p = fmaf(gl, msk, p);

#pragma unroll
        for (int off = 16; off > 0; off >>= 1)
            p += __shfl_xor_sync(0xffffffffu, p, off);
        p += cb;

        if (l == 0) g_energ[b * T + tw0 + i] = p;

        if (p > m) {
            const float sc = __expf(m - p);
            s = fmaf(s, sc, 1.f);
#pragma unroll
            for (int j = 0; j < 8; j++) cx[j] *= sc;
            m = p;
            cx[0] += a0.x; cx[1] += a0.y; cx[2] += a0.z; cx[3] += a0.w;
            cx[4] += a1.x; cx[5] += a1.y; cx[6] += a1.z; cx[7] += a1.w;
        } else {
            const float pe = __expf(p - m);
            s += pe;
            cx[0] = fmaf(pe, a0.x, cx[0]); cx[1] = fmaf(pe, a0.y, cx[1]);
            cx[2] = fmaf(pe, a0.z, cx[2]); cx[3] = fmaf(pe, a0.w, cx[3]);
            cx[4] = fmaf(pe, a1.x, cx[4]); cx[5] = fmaf(pe, a1.y, cx[5]);
            cx[6] = fmaf(pe, a1.z, cx[6]); cx[7] = fmaf(pe, a1.w, cx[7]);
        }
    }

    // ---- block epilogue: merge 8 warp partials ----
    if (l == 0) { red_m[w] = m; red_s[w] = s; }
    *(float4*)(&red_ctx[w][l * 8])     = *(float4*)(&cx[0]);
    *(float4*)(&red_ctx[w][l * 8 + 4]) = *(float4*)(&cx[4]);
    __syncthreads();

    float M = red_m[0];
#pragma unroll
    for (int j = 1; j < WPB; j++) M = fmaxf(M, red_m[j]);
    float S = 0.f, C = 0.f;
#pragma unroll
    for (int j = 0; j < WPB; j++) {
        const float wj = __expf(red_m[j] - M);
        S = fmaf(red_s[j], wj, S);
        C = fmaf(wj, red_ctx[j][tid], C);
    }

    const int pidx = b * NCH + ch;
    g_pctx[pidx * DIM + tid] = C;
    if (tid == 0) { g_pm[pidx] = M; g_ps[pidx] = S; }

    // ---- fused finish: last block of this batch does combine + outputs ----
    __threadfence();
    if (tid == 0) is_last = (atomicAdd(&g_done[b], 1) == NCH - 1);
    __syncthreads();
    if (!is_last) return;
    __threadfence();   // acquire side: make other blocks' writes visible

    // reuse red_m/red_s shared space for the chunk partials
    __shared__ float fsm[NCH], fss[NCH];
    if (tid < NCH) { fsm[tid] = g_pm[b * NCH + tid]; fss[tid] = g_ps[b * NCH + tid]; }
    __syncthreads();

    float FM = fsm[0];
#pragma unroll
    for (int j = 1; j < NCH; j++) FM = fmaxf(FM, fsm[j]);
    float FS = 0.f;
#pragma unroll
    for (int j = 0; j < NCH; j++) FS = fmaf(fss[j], __expf(fsm[j] - FM), FS);
    const float invS = 1.0f / FS;

    float ctx = 0.f;
#pragma unroll
    for (int j = 0; j < NCH; j++)
        ctx = fmaf(__expf(fsm[j] - FM), g_pctx[(b * NCH + j) * DIM + tid], ctx);
    out[b * DIM + tid] = ctx * invS;

    const float4* ep = (const float4*)(g_energ + (size_t)b * T);
    float4*       op = (float4*)(out + (size_t)B * DIM + (size_t)b * T);
#pragma unroll
    for (int i = tid; i < T / 4; i += 256) {
        float4 e = ep[i];
        float4 r;
        r.x = __expf(e.x - FM) * invS;
        r.y = __expf(e.y - FM) * invS;
        r.z = __expf(e.z - FM) * invS;
        r.w = __expf(e.w - FM) * invS;
        op[i] = r;
    }
}

// ---------------------------------------------------------------------------
extern "C" void kernel_launch(void* const* d_in, const int* in_sizes, int n_in,
                              void* d_out, int out_size) {
    const float* q     = (const float*)d_in[0];  // (1,64,256)
    const float* enc   = (const float*)d_in[1];  // (4096,64,256)
    const float* mask  = (const float*)d_in[2];  // (64,4096,1)
    const float* Ww    = (const float*)d_in[3];  // (256,256)
    const float* Lw    = (const float*)d_in[4];  // (256,32)
    const float* convw = (const float*)d_in[5];  // (32,1,31)
    const float* convb = (const float*)d_in[6];  // (32,)
    float* out = (float*)d_out;                  // context(16384) ++ attn(262144)

    dim3 gridA(B, 9);
    prep_kernel<<<gridA, 256>>>(q, Ww, Lw, convw, convb);

    // main kernel with programmatic dependent launch (overlaps prep tail)
    cudaLaunchConfig_t cfg = {};
    cfg.gridDim  = dim3(B, NCH);
    cfg.blockDim = dim3(256);
    cfg.dynamicSmemBytes = 0;
    cfg.stream = 0;
    cudaLaunchAttribute attrs[1];
    attrs[0].id = cudaLaunchAttributeProgrammaticStreamSerialization;
    attrs[0].val.programmaticStreamSerializationAllowed = 1;
    cfg.attrs = attrs;
    cfg.numAttrs = 1;
    cudaLaunchKernelEx(&cfg, energy_ctx_kernel, enc, mask, out);
}